// round 1
// baseline (speedup 1.0000x reference)
#include <cuda_runtime.h>
#include <cstdint>

#define HD 128
#define MAXN 50000
#define MAXG 64

// ---------------- scratch (static __device__ arrays; no allocation) ----------
__device__ __align__(16) float g_A   [(size_t)MAXN * HD];
__device__ __align__(16) float g_Bv  [(size_t)MAXN * HD];
__device__ __align__(16) float g_aggr[(size_t)MAXN * HD];
__device__ __align__(16) float g_h1  [(size_t)MAXN * HD];
__device__ __align__(16) float g_R   [(size_t)MAXN * HD];
__device__ __align__(16) float g_h2  [(size_t)MAXN * HD];
__device__ __align__(16) float g_pool[(size_t)MAXG * HD];

// ---------------- helpers ----------------------------------------------------
__device__ __forceinline__ void red_add_v4(float* dst, float4 v) {
#if __CUDA_ARCH__ >= 900
    asm volatile("red.global.add.v4.f32 [%0], {%1,%2,%3,%4};"
                 :: "l"(dst), "f"(v.x), "f"(v.y), "f"(v.z), "f"(v.w)
                 : "memory");
#else
    atomicAdd(dst + 0, v.x); atomicAdd(dst + 1, v.y);
    atomicAdd(dst + 2, v.z); atomicAdd(dst + 3, v.w);
#endif
}

// ---------------- zero kernel -------------------------------------------------
__global__ void zero_kernel(float* __restrict__ p, int n4) {
    int i = blockIdx.x * blockDim.x + threadIdx.x;
    int stride = gridDim.x * blockDim.x;
    float4 z = make_float4(0.f, 0.f, 0.f, 0.f);
    for (; i < n4; i += stride) ((float4*)p)[i] = z;
}

// ---------------- generic SGEMM ----------------------------------------------
// C[n, HD] = (resid? resid:0) + act( X0@W0 + (X1? X1@W1:0) + (bias?bias:0) )
// All row-major with HD=128 columns. W0/W1 are 128x128 blocks.
// BM=128, BN=128, BK=8, TM=TN=8, 256 threads.
__global__ void __launch_bounds__(256)
sgemm128(const float* __restrict__ X0, const float* __restrict__ W0,
         const float* __restrict__ X1, const float* __restrict__ W1,
         const float* __restrict__ bias, const float* __restrict__ resid,
         float* __restrict__ C, int nrows, int do_relu)
{
    const int BM = 128, BK = 8, TM = 8, TN = 8;
    __shared__ float As[BK][BM + 4];   // +4 floats keeps rows 16B-aligned
    __shared__ float Ws[BK][128];

    int tid  = threadIdx.x;
    int row0 = blockIdx.x * BM;
    int tx = tid & 15;        // 0..15 -> cols tx*8..+7
    int ty = tid >> 4;        // 0..15 -> rows ty*8..+7

    // load indices
    int lr = tid >> 1;            // 0..127 : tile row
    int lk = (tid & 1) * 4;       // 0 or 4 : k offset
    int wr = tid >> 5;            // 0..7   : k row
    int wc = (tid & 31) * 4;      // 0..124 : col

    float acc[TM][TN];
    #pragma unroll
    for (int i = 0; i < TM; i++)
        #pragma unroll
        for (int j = 0; j < TN; j++) acc[i][j] = 0.f;

    int npass = (X1 != nullptr) ? 2 : 1;
    for (int pass = 0; pass < npass; ++pass) {
        const float* X = pass ? X1 : X0;
        const float* W = pass ? W1 : W0;
        for (int k0 = 0; k0 < HD; k0 += BK) {
            float4 xv = make_float4(0.f, 0.f, 0.f, 0.f);
            int gr = row0 + lr;
            if (gr < nrows)
                xv = *(const float4*)(X + (size_t)gr * HD + k0 + lk);
            As[lk + 0][lr] = xv.x;
            As[lk + 1][lr] = xv.y;
            As[lk + 2][lr] = xv.z;
            As[lk + 3][lr] = xv.w;

            float4 wv = *(const float4*)(W + (size_t)(k0 + wr) * HD + wc);
            *(float4*)&Ws[wr][wc] = wv;
            __syncthreads();

            #pragma unroll
            for (int kk = 0; kk < BK; ++kk) {
                float a[TM], b[TN];
                #pragma unroll
                for (int i = 0; i < TM; i++) a[i] = As[kk][ty * TM + i];
                #pragma unroll
                for (int j = 0; j < TN; j++) b[j] = Ws[kk][tx * TN + j];
                #pragma unroll
                for (int i = 0; i < TM; i++)
                    #pragma unroll
                    for (int j = 0; j < TN; j++)
                        acc[i][j] = fmaf(a[i], b[j], acc[i][j]);
            }
            __syncthreads();
        }
    }

    // epilogue
    #pragma unroll
    for (int i = 0; i < TM; i++) {
        int gr = row0 + ty * TM + i;
        if (gr >= nrows) break;
        #pragma unroll
        for (int j = 0; j < TN; j += 4) {
            int gc = tx * TN + j;
            float4 v = make_float4(acc[i][j], acc[i][j + 1],
                                   acc[i][j + 2], acc[i][j + 3]);
            if (bias) {
                v.x += bias[gc];     v.y += bias[gc + 1];
                v.z += bias[gc + 2]; v.w += bias[gc + 3];
            }
            if (do_relu) {
                v.x = fmaxf(v.x, 0.f); v.y = fmaxf(v.y, 0.f);
                v.z = fmaxf(v.z, 0.f); v.w = fmaxf(v.w, 0.f);
            }
            if (resid) {
                float4 r = *(const float4*)(resid + (size_t)gr * HD + gc);
                v.x += r.x; v.y += r.y; v.z += r.z; v.w += r.w;
            }
            *(float4*)(C + (size_t)gr * HD + gc) = v;
        }
    }
}

// ---------------- per-edge message + scatter ---------------------------------
// msg = relu(A[row] + B[col] + dist*w_d + b);  aggr[col] += msg
// one warp per edge, lane handles 4 features.
__global__ void __launch_bounds__(256)
edge_kernel(const float* __restrict__ A, const float* __restrict__ B,
            const float* __restrict__ dist,
            const int* __restrict__ row, const int* __restrict__ col,
            const float* __restrict__ wd, const float* __restrict__ bm,
            float* __restrict__ aggr, int nedges)
{
    __shared__ __align__(16) float swd[HD];
    __shared__ __align__(16) float sbm[HD];
    int tid = threadIdx.x;
    if (tid < HD) { swd[tid] = wd[tid]; sbm[tid] = bm[tid]; }
    __syncthreads();

    int lane = tid & 31;
    int e = blockIdx.x * 8 + (tid >> 5);
    if (e >= nedges) return;

    int r = __ldg(row + e);
    int c = __ldg(col + e);
    float d = __ldg(dist + e);
    int f = lane * 4;

    float4 a = *(const float4*)(A + (size_t)r * HD + f);
    float4 b = *(const float4*)(B + (size_t)c * HD + f);
    float4 w = *(const float4*)(swd + f);
    float4 bb = *(const float4*)(sbm + f);

    float4 m;
    m.x = fmaxf(fmaf(d, w.x, a.x + b.x + bb.x), 0.f);
    m.y = fmaxf(fmaf(d, w.y, a.y + b.y + bb.y), 0.f);
    m.z = fmaxf(fmaf(d, w.z, a.z + b.z + bb.z), 0.f);
    m.w = fmaxf(fmaf(d, w.w, a.w + b.w + bb.w), 0.f);

    red_add_v4(aggr + (size_t)c * HD + f, m);
}

// ---------------- per-graph pooling ------------------------------------------
__global__ void __launch_bounds__(256)
pool_kernel(const float* __restrict__ h, const int* __restrict__ batch,
            float* __restrict__ pool, int n)
{
    int warp = (blockIdx.x * blockDim.x + threadIdx.x) >> 5;
    int lane = threadIdx.x & 31;
    if (warp >= n) return;
    int g = __ldg(batch + warp);
    float4 v = *(const float4*)(h + (size_t)warp * HD + lane * 4);
    red_add_v4(pool + (size_t)g * HD + lane * 4, v);
}

// ---------------- prediction head --------------------------------------------
// out[b] = relu(pool[b]@w_p1 + b_p1) @ w_p2 + b_p2   (T=1)
__global__ void __launch_bounds__(128)
head_kernel(const float* __restrict__ pool,
            const float* __restrict__ wp1, const float* __restrict__ bp1,
            const float* __restrict__ wp2, const float* __restrict__ bp2,
            float* __restrict__ out)
{
    int b = blockIdx.x;
    int t = threadIdx.x;          // 128
    __shared__ float sg[HD];
    __shared__ float red[HD];

    sg[t] = pool[(size_t)b * HD + t];
    __syncthreads();

    float acc = bp1[t];
    #pragma unroll 8
    for (int k = 0; k < HD; k++)
        acc = fmaf(sg[k], wp1[(size_t)k * HD + t], acc);
    acc = fmaxf(acc, 0.f) * wp2[t];

    red[t] = acc;
    __syncthreads();
    for (int s = 64; s > 0; s >>= 1) {
        if (t < s) red[t] += red[t + s];
        __syncthreads();
    }
    if (t == 0) out[b] = red[0] + bp2[0];
}

// ---------------- host side ---------------------------------------------------
extern "C" void kernel_launch(void* const* d_in, const int* in_sizes, int n_in,
                              void* d_out, int out_size)
{
    const float* x      = (const float*)d_in[0];
    const float* edist  = (const float*)d_in[1];
    const int*   eidx   = (const int*)  d_in[2];
    const int*   batch  = (const int*)  d_in[3];
    const float* wres1  = (const float*)d_in[4];
    const float* wmsg1  = (const float*)d_in[5];
    const float* bmsg1  = (const float*)d_in[6];
    const float* wupd1  = (const float*)d_in[7];
    const float* bupd1  = (const float*)d_in[8];
    const float* wres2  = (const float*)d_in[9];
    const float* wmsg2  = (const float*)d_in[10];
    const float* bmsg2  = (const float*)d_in[11];
    const float* wupd2  = (const float*)d_in[12];
    const float* bupd2  = (const float*)d_in[13];
    const float* wp1    = (const float*)d_in[14];
    const float* bp1    = (const float*)d_in[15];
    const float* wp2    = (const float*)d_in[16];
    const float* bp2    = (const float*)d_in[17];
    float* out = (float*)d_out;

    int N = in_sizes[0] / HD;
    int E = in_sizes[1];
    int G = out_size;   // T == 1
    const int* erow = eidx;
    const int* ecol = eidx + E;

    float *A, *B, *AG, *H1, *R, *H2, *P;
    cudaGetSymbolAddress((void**)&A,  g_A);
    cudaGetSymbolAddress((void**)&B,  g_Bv);
    cudaGetSymbolAddress((void**)&AG, g_aggr);
    cudaGetSymbolAddress((void**)&H1, g_h1);
    cudaGetSymbolAddress((void**)&R,  g_R);
    cudaGetSymbolAddress((void**)&H2, g_h2);
    cudaGetSymbolAddress((void**)&P,  g_pool);

    dim3 gemm_grid((N + 127) / 128);
    int edge_blocks = (E + 7) / 8;
    int nh4 = (N * HD) / 4;
    int zero_blocks = 1024;

    // ---------- layer 1 ----------
    zero_kernel<<<zero_blocks, 256>>>(AG, nh4);
    sgemm128<<<gemm_grid, 256>>>(x, wmsg1,            nullptr, nullptr, nullptr, nullptr, A,  N, 0);
    sgemm128<<<gemm_grid, 256>>>(x, wmsg1 + 128 * HD, nullptr, nullptr, nullptr, nullptr, B,  N, 0);
    edge_kernel<<<edge_blocks, 256>>>(A, B, edist, erow, ecol,
                                      wmsg1 + 256 * HD, bmsg1, AG, E);
    sgemm128<<<gemm_grid, 256>>>(x, wres1, nullptr, nullptr, nullptr, nullptr, R, N, 0);
    sgemm128<<<gemm_grid, 256>>>(x, wupd1, AG, wupd1 + 128 * HD, bupd1, R, H1, N, 1);

    // ---------- layer 2 ----------
    zero_kernel<<<zero_blocks, 256>>>(AG, nh4);
    sgemm128<<<gemm_grid, 256>>>(H1, wmsg2,            nullptr, nullptr, nullptr, nullptr, A, N, 0);
    sgemm128<<<gemm_grid, 256>>>(H1, wmsg2 + 128 * HD, nullptr, nullptr, nullptr, nullptr, B, N, 0);
    edge_kernel<<<edge_blocks, 256>>>(A, B, edist, erow, ecol,
                                      wmsg2 + 256 * HD, bmsg2, AG, E);
    sgemm128<<<gemm_grid, 256>>>(H1, wres2, nullptr, nullptr, nullptr, nullptr, R, N, 0);
    sgemm128<<<gemm_grid, 256>>>(H1, wupd2, AG, wupd2 + 128 * HD, bupd2, R, H2, N, 1);

    // ---------- pooling + head ----------
    zero_kernel<<<4, 256>>>(P, (G * HD) / 4);
    int pool_blocks = (N * 32 + 255) / 256;
    pool_kernel<<<pool_blocks, 256>>>(H2, batch, P, N);
    head_kernel<<<G, 128>>>(P, wp1, bp1, wp2, bp2, out);
}

// round 4
// speedup vs baseline: 1.0925x; 1.0925x over previous
#include <cuda_runtime.h>
#include <cstdint>

#define HD 128
#define MAXN 50000
#define MAXG 64

// ---------------- scratch (static __device__ arrays; no allocation) ----------
__device__ __align__(16) float g_A   [(size_t)MAXN * HD];
__device__ __align__(16) float g_Bv  [(size_t)MAXN * HD];
__device__ __align__(16) float g_aggr[(size_t)MAXN * HD];
__device__ __align__(16) float g_h1  [(size_t)MAXN * HD];
__device__ __align__(16) float g_R   [(size_t)MAXN * HD];
__device__ __align__(16) float g_h2  [(size_t)MAXN * HD];
__device__ __align__(16) float g_pool[(size_t)MAXG * HD];

// ---------------- helpers ----------------------------------------------------
__device__ __forceinline__ void red_add_v4(float* dst, float4 v) {
    asm volatile("red.global.add.v4.f32 [%0], {%1,%2,%3,%4};"
                 :: "l"(dst), "f"(v.x), "f"(v.y), "f"(v.z), "f"(v.w)
                 : "memory");
}

// ---------------- zero kernel -------------------------------------------------
__global__ void zero_kernel(float* __restrict__ p, int n4) {
    int i = blockIdx.x * blockDim.x + threadIdx.x;
    int stride = gridDim.x * blockDim.x;
    float4 z = make_float4(0.f, 0.f, 0.f, 0.f);
    for (; i < n4; i += stride) ((float4*)p)[i] = z;
}

// ---------------- double-buffered SGEMM --------------------------------------
// C[n, HD] = (resid? resid:0) + act( X0@W0 + (X1? X1@W1:0) + (bias?bias:0) )
// Row-major, HD=128 columns, W blocks are 128x128 with row stride HD.
// BM=128, BN=128, BK=16, TM=TN=8, 256 threads, 2-stage smem pipeline.
__global__ void __launch_bounds__(256)
sgemm128(const float* __restrict__ X0, const float* __restrict__ W0,
         const float* __restrict__ X1, const float* __restrict__ W1,
         const float* __restrict__ bias, const float* __restrict__ resid,
         float* __restrict__ C, int nrows, int do_relu)
{
    const int BK = 16;
    __shared__ float As[2][BK][128];   // transposed: As[k][m]
    __shared__ float Ws[2][BK][128];   // natural:    Ws[k][n]

    int t = threadIdx.x;
    int row0 = blockIdx.x * 128;
    int tx = t & 15;          // 0..15 -> output cols tx*8..+7
    int ty = t >> 4;          // 0..15 -> output rows ty*8..+7

    // A load indices: each thread loads 2 float4 (one tile row, two k-quads)
    int ar = t & 127;             // tile row
    int ak = (t >> 7) * 4;        // 0 or 4 (second float4 at ak+8)
    // W load indices
    int wk = t >> 5;              // 0..7 (second float4 at wk+8)
    int wn = (t & 31) * 4;

    int npass = (X1 != nullptr) ? 2 : 1;
    int nsteps = npass * 8;       // 8 BK-steps per 128-K pass

    float acc[8][8];
    #pragma unroll
    for (int i = 0; i < 8; i++)
        #pragma unroll
        for (int j = 0; j < 8; j++) acc[i][j] = 0.f;

    int gr = row0 + ar;
    bool arow_ok = (gr < nrows);
    const float* Xrow0 = X0 + (size_t)gr * HD;
    const float* Xrow1 = (X1 ? X1 + (size_t)gr * HD : Xrow0);

    float4 xa0, xa1, wb0, wb1;

    // ---- prologue: load + store stage 0 ----
    {
        xa0 = xa1 = make_float4(0.f, 0.f, 0.f, 0.f);
        if (arow_ok) {
            xa0 = *(const float4*)(Xrow0 + ak);
            xa1 = *(const float4*)(Xrow0 + ak + 8);
        }
        wb0 = *(const float4*)(W0 + (size_t)wk * HD + wn);
        wb1 = *(const float4*)(W0 + (size_t)(wk + 8) * HD + wn);

        As[0][ak + 0][ar] = xa0.x;  As[0][ak + 1][ar] = xa0.y;
        As[0][ak + 2][ar] = xa0.z;  As[0][ak + 3][ar] = xa0.w;
        As[0][ak + 8][ar] = xa1.x;  As[0][ak + 9][ar] = xa1.y;
        As[0][ak +10][ar] = xa1.z;  As[0][ak +11][ar] = xa1.w;
        *(float4*)&Ws[0][wk][wn]     = wb0;
        *(float4*)&Ws[0][wk + 8][wn] = wb1;
    }

    for (int s = 0; s < nsteps; ++s) {
        __syncthreads();
        int cur = s & 1, nxt = cur ^ 1;
        bool more = (s + 1 < nsteps);

        if (more) {
            int sn = s + 1;
            const float* Xr = (sn >= 8) ? Xrow1 : Xrow0;
            const float* W  = (sn >= 8) ? W1    : W0;
            int k0 = (sn & 7) * BK;
            xa0 = xa1 = make_float4(0.f, 0.f, 0.f, 0.f);
            if (arow_ok) {
                xa0 = *(const float4*)(Xr + k0 + ak);
                xa1 = *(const float4*)(Xr + k0 + ak + 8);
            }
            wb0 = *(const float4*)(W + (size_t)(k0 + wk) * HD + wn);
            wb1 = *(const float4*)(W + (size_t)(k0 + wk + 8) * HD + wn);
        }

        #pragma unroll
        for (int kk = 0; kk < BK; ++kk) {
            float4 a0 = *(const float4*)&As[cur][kk][ty * 8];
            float4 a1 = *(const float4*)&As[cur][kk][ty * 8 + 4];
            float4 b0 = *(const float4*)&Ws[cur][kk][tx * 8];
            float4 b1 = *(const float4*)&Ws[cur][kk][tx * 8 + 4];
            float a[8] = {a0.x,a0.y,a0.z,a0.w,a1.x,a1.y,a1.z,a1.w};
            float b[8] = {b0.x,b0.y,b0.z,b0.w,b1.x,b1.y,b1.z,b1.w};
            #pragma unroll
            for (int i = 0; i < 8; i++)
                #pragma unroll
                for (int j = 0; j < 8; j++)
                    acc[i][j] = fmaf(a[i], b[j], acc[i][j]);
        }

        if (more) {
            As[nxt][ak + 0][ar] = xa0.x;  As[nxt][ak + 1][ar] = xa0.y;
            As[nxt][ak + 2][ar] = xa0.z;  As[nxt][ak + 3][ar] = xa0.w;
            As[nxt][ak + 8][ar] = xa1.x;  As[nxt][ak + 9][ar] = xa1.y;
            As[nxt][ak +10][ar] = xa1.z;  As[nxt][ak +11][ar] = xa1.w;
            *(float4*)&Ws[nxt][wk][wn]     = wb0;
            *(float4*)&Ws[nxt][wk + 8][wn] = wb1;
        }
    }

    // epilogue
    #pragma unroll
    for (int i = 0; i < 8; i++) {
        int orow = row0 + ty * 8 + i;
        if (orow >= nrows) break;
        #pragma unroll
        for (int j = 0; j < 8; j += 4) {
            int oc = tx * 8 + j;
            float4 v = make_float4(acc[i][j], acc[i][j + 1],
                                   acc[i][j + 2], acc[i][j + 3]);
            if (bias) {
                v.x += bias[oc];     v.y += bias[oc + 1];
                v.z += bias[oc + 2]; v.w += bias[oc + 3];
            }
            if (do_relu) {
                v.x = fmaxf(v.x, 0.f); v.y = fmaxf(v.y, 0.f);
                v.z = fmaxf(v.z, 0.f); v.w = fmaxf(v.w, 0.f);
            }
            if (resid) {
                float4 r = *(const float4*)(resid + (size_t)orow * HD + oc);
                v.x += r.x; v.y += r.y; v.z += r.z; v.w += r.w;
            }
            *(float4*)(C + (size_t)orow * HD + oc) = v;
        }
    }
}

// ---------------- per-edge message + scatter ---------------------------------
// msg = relu(A[row] + B'[col] + dist*w_d);  aggr[col] += msg
// (b_msg pre-folded into B' by the GEMM epilogue)
// One warp handles 2 edges (4 independent 512B gathers in flight).
__global__ void __launch_bounds__(256)
edge_kernel(const float* __restrict__ A, const float* __restrict__ B,
            const float* __restrict__ dist,
            const int* __restrict__ row, const int* __restrict__ col,
            const float* __restrict__ wd,
            float* __restrict__ aggr, int nedges)
{
    __shared__ __align__(16) float swd[HD];
    int t = threadIdx.x;
    if (t < HD) swd[t] = wd[t];
    __syncthreads();

    int lane = t & 31;
    int f = lane * 4;
    float4 w = *(const float4*)(swd + f);

    int gw = blockIdx.x * 8 + (t >> 5);   // global warp id
    int e0 = gw * 2;
    if (e0 >= nedges) return;
    int e1 = e0 + 1;
    bool has1 = (e1 < nedges);

    int   r0 = __ldg(row + e0);
    int   c0 = __ldg(col + e0);
    float d0 = __ldg(dist + e0);
    int   r1 = has1 ? __ldg(row + e1) : r0;
    int   c1 = has1 ? __ldg(col + e1) : c0;
    float d1 = has1 ? __ldg(dist + e1) : 0.f;

    float4 a0 = *(const float4*)(A + (size_t)r0 * HD + f);
    float4 b0 = *(const float4*)(B + (size_t)c0 * HD + f);
    float4 a1 = *(const float4*)(A + (size_t)r1 * HD + f);
    float4 b1 = *(const float4*)(B + (size_t)c1 * HD + f);

    float4 m0, m1;
    m0.x = fmaxf(fmaf(d0, w.x, a0.x + b0.x), 0.f);
    m0.y = fmaxf(fmaf(d0, w.y, a0.y + b0.y), 0.f);
    m0.z = fmaxf(fmaf(d0, w.z, a0.z + b0.z), 0.f);
    m0.w = fmaxf(fmaf(d0, w.w, a0.w + b0.w), 0.f);
    m1.x = fmaxf(fmaf(d1, w.x, a1.x + b1.x), 0.f);
    m1.y = fmaxf(fmaf(d1, w.y, a1.y + b1.y), 0.f);
    m1.z = fmaxf(fmaf(d1, w.z, a1.z + b1.z), 0.f);
    m1.w = fmaxf(fmaf(d1, w.w, a1.w + b1.w), 0.f);

    red_add_v4(aggr + (size_t)c0 * HD + f, m0);
    if (has1) red_add_v4(aggr + (size_t)c1 * HD + f, m1);
}

// ---------------- per-graph pooling ------------------------------------------
__global__ void __launch_bounds__(256)
pool_kernel(const float* __restrict__ h, const int* __restrict__ batch,
            float* __restrict__ pool, int n)
{
    int warp = (blockIdx.x * blockDim.x + threadIdx.x) >> 5;
    int lane = threadIdx.x & 31;
    if (warp >= n) return;
    int g = __ldg(batch + warp);
    float4 v = *(const float4*)(h + (size_t)warp * HD + lane * 4);
    red_add_v4(pool + (size_t)g * HD + lane * 4, v);
}

// ---------------- prediction head --------------------------------------------
__global__ void __launch_bounds__(128)
head_kernel(const float* __restrict__ pool,
            const float* __restrict__ wp1, const float* __restrict__ bp1,
            const float* __restrict__ wp2, const float* __restrict__ bp2,
            float* __restrict__ out)
{
    int b = blockIdx.x;
    int t = threadIdx.x;          // 128
    __shared__ float sg[HD];
    __shared__ float red[HD];

    sg[t] = pool[(size_t)b * HD + t];
    __syncthreads();

    float acc = bp1[t];
    #pragma unroll 8
    for (int k = 0; k < HD; k++)
        acc = fmaf(sg[k], wp1[(size_t)k * HD + t], acc);
    acc = fmaxf(acc, 0.f) * wp2[t];

    red[t] = acc;
    __syncthreads();
    for (int s = 64; s > 0; s >>= 1) {
        if (t < s) red[t] += red[t + s];
        __syncthreads();
    }
    if (t == 0) out[b] = red[0] + bp2[0];
}

// ---------------- host side ---------------------------------------------------
extern "C" void kernel_launch(void* const* d_in, const int* in_sizes, int n_in,
                              void* d_out, int out_size)
{
    const float* x      = (const float*)d_in[0];
    const float* edist  = (const float*)d_in[1];
    const int*   eidx   = (const int*)  d_in[2];
    const int*   batch  = (const int*)  d_in[3];
    const float* wres1  = (const float*)d_in[4];
    const float* wmsg1  = (const float*)d_in[5];
    const float* bmsg1  = (const float*)d_in[6];
    const float* wupd1  = (const float*)d_in[7];
    const float* bupd1  = (const float*)d_in[8];
    const float* wres2  = (const float*)d_in[9];
    const float* wmsg2  = (const float*)d_in[10];
    const float* bmsg2  = (const float*)d_in[11];
    const float* wupd2  = (const float*)d_in[12];
    const float* bupd2  = (const float*)d_in[13];
    const float* wp1    = (const float*)d_in[14];
    const float* bp1    = (const float*)d_in[15];
    const float* wp2    = (const float*)d_in[16];
    const float* bp2    = (const float*)d_in[17];
    float* out = (float*)d_out;

    int N = in_sizes[0] / HD;
    int E = in_sizes[1];
    int G = out_size;   // T == 1
    const int* erow = eidx;
    const int* ecol = eidx + E;

    float *A, *B, *AG, *H1, *R, *H2, *P;
    cudaGetSymbolAddress((void**)&A,  g_A);
    cudaGetSymbolAddress((void**)&B,  g_Bv);
    cudaGetSymbolAddress((void**)&AG, g_aggr);
    cudaGetSymbolAddress((void**)&H1, g_h1);
    cudaGetSymbolAddress((void**)&R,  g_R);
    cudaGetSymbolAddress((void**)&H2, g_h2);
    cudaGetSymbolAddress((void**)&P,  g_pool);

    dim3 gemm_grid((N + 127) / 128);
    int edge_blocks = (E + 15) / 16;   // 2 edges per warp, 8 warps per block
    int nh4 = (N * HD) / 4;
    int zero_blocks = 1024;

    // ---------- layer 1 ----------
    zero_kernel<<<zero_blocks, 256>>>(AG, nh4);
    sgemm128<<<gemm_grid, 256>>>(x, wmsg1,            nullptr, nullptr, nullptr, nullptr, A,  N, 0);
    sgemm128<<<gemm_grid, 256>>>(x, wmsg1 + 128 * HD, nullptr, nullptr, bmsg1,   nullptr, B,  N, 0);
    edge_kernel<<<edge_blocks, 256>>>(A, B, edist, erow, ecol, wmsg1 + 256 * HD, AG, E);
    sgemm128<<<gemm_grid, 256>>>(x, wres1, nullptr, nullptr, nullptr, nullptr, R, N, 0);
    sgemm128<<<gemm_grid, 256>>>(x, wupd1, AG, wupd1 + 128 * HD, bupd1, R, H1, N, 1);

    // ---------- layer 2 ----------
    zero_kernel<<<zero_blocks, 256>>>(AG, nh4);
    sgemm128<<<gemm_grid, 256>>>(H1, wmsg2,            nullptr, nullptr, nullptr, nullptr, A, N, 0);
    sgemm128<<<gemm_grid, 256>>>(H1, wmsg2 + 128 * HD, nullptr, nullptr, bmsg2,   nullptr, B, N, 0);
    edge_kernel<<<edge_blocks, 256>>>(A, B, edist, erow, ecol, wmsg2 + 256 * HD, AG, E);
    sgemm128<<<gemm_grid, 256>>>(H1, wres2, nullptr, nullptr, nullptr, nullptr, R, N, 0);
    sgemm128<<<gemm_grid, 256>>>(H1, wupd2, AG, wupd2 + 128 * HD, bupd2, R, H2, N, 1);

    // ---------- pooling + head ----------
    zero_kernel<<<4, 256>>>(P, (G * HD) / 4);
    int pool_blocks = (N * 32 + 255) / 256;
    pool_kernel<<<pool_blocks, 256>>>(H2, batch, P, N);
    head_kernel<<<G, 128>>>(P, wp1, bp1, wp2, bp2, out);
}

// round 6
// speedup vs baseline: 1.5786x; 1.4450x over previous
#include <cuda_runtime.h>
#include <cuda_bf16.h>
#include <cstdint>

#define HD 128
#define MAXN 50000
#define MAXG 64

// ---------------- scratch (static __device__ arrays; no allocation) ----------
__device__ __align__(16) float g_A   [(size_t)MAXN * HD];
__device__ __align__(16) float g_Bv  [(size_t)MAXN * HD];
__device__ __align__(16) float g_aggr[(size_t)MAXN * HD];
__device__ __align__(16) float g_h1  [(size_t)MAXN * HD];
__device__ __align__(16) float g_R   [(size_t)MAXN * HD];
__device__ __align__(16) float g_h2  [(size_t)MAXN * HD];
__device__ __align__(16) float g_pool[(size_t)MAXG * HD];
// augmented bf16 activations: [n, 384] = [hi(128) | lo(128) | hi(128)]
__device__ __align__(16) __nv_bfloat16 g_xaug[(size_t)MAXN * 384];
__device__ __align__(16) __nv_bfloat16 g_gaug[(size_t)MAXN * 384];
// augmented weights, [n, k'] row-major
__device__ __align__(16) __nv_bfloat16 g_wab [2][256 * 384];
__device__ __align__(16) __nv_bfloat16 g_wres[2][128 * 384];
__device__ __align__(16) __nv_bfloat16 g_wupd[2][128 * 768];

// ---------------- helpers ----------------------------------------------------
__device__ __forceinline__ void red_add_v4(float* dst, float4 v) {
    asm volatile("red.global.add.v4.f32 [%0], {%1,%2,%3,%4};"
                 :: "l"(dst), "f"(v.x), "f"(v.y), "f"(v.z), "f"(v.w) : "memory");
}
__device__ __forceinline__ uint32_t smem_u32(const void* p) {
    uint32_t a;
    asm("{ .reg .u64 t; cvta.to.shared.u64 t, %1; cvt.u32.u64 %0, t; }"
        : "=r"(a) : "l"(p));
    return a;
}
__device__ __forceinline__ void cp_async16(uint32_t dst, const void* src) {
    asm volatile("cp.async.ca.shared.global [%0], [%1], 16;"
                 :: "r"(dst), "l"(src) : "memory");
}
__device__ __forceinline__ void cp_commit() {
    asm volatile("cp.async.commit_group;" ::: "memory");
}
template <int N>
__device__ __forceinline__ void cp_wait() {
    asm volatile("cp.async.wait_group %0;" :: "n"(N) : "memory");
}
__device__ __forceinline__ void mma16816(float* d, const uint32_t* a,
                                         uint32_t b0, uint32_t b1) {
    asm volatile("mma.sync.aligned.m16n8k16.row.col.f32.bf16.bf16.f32 "
                 "{%0,%1,%2,%3}, {%4,%5,%6,%7}, {%8,%9}, {%0,%1,%2,%3};"
                 : "+f"(d[0]), "+f"(d[1]), "+f"(d[2]), "+f"(d[3])
                 : "r"(a[0]), "r"(a[1]), "r"(a[2]), "r"(a[3]),
                   "r"(b0), "r"(b1));
}

// ---------------- bf16 tensor-core GEMM ---------------------------------------
// C[128 x 128 tile] = A_aug @ W_aug^T over K' (1 or 2 passes of 384).
// A_aug: [m, 384] bf16 row-major. W: [n, wstride] bf16 row-major (B operand).
// smem tile rows padded to 40 bf16 (80 B) -> conflict-free frag loads.
// modes: 0 = plain store (R). 1 = AB (y==0 -> out0; y==1 -> out1 + bias).
//        2 = UPD: out0 = resid + relu(acc + bias)
#define SROW 40
#define SBUF (128 * SROW)              // elements per buffer
#define SBUFB (SBUF * 2)               // bytes per buffer = 10240

__device__ __forceinline__ void stage_load(
    int s, int t, int row0, int nrows,
    const __nv_bfloat16* __restrict__ A0, const __nv_bfloat16* __restrict__ A1,
    const __nv_bfloat16* __restrict__ Wp, int wstride,
    uint32_t sAu, uint32_t sBu)
{
    int buf = s & 1;
    int kk = (s % 12) * 32;
    int koff = (s / 12) * 384 + kk;
    const __nv_bfloat16* Asrc = (s < 12) ? A0 : A1;
    uint32_t dA = sAu + (uint32_t)buf * SBUFB;
    uint32_t dB = sBu + (uint32_t)buf * SBUFB;
    #pragma unroll
    for (int i = t; i < 512; i += 256) {
        int r = i >> 2, q = i & 3;
        int gr = row0 + r; if (gr >= nrows) gr = nrows - 1;
        cp_async16(dA + r * 80 + q * 16, Asrc + (size_t)gr * 384 + kk + q * 8);
        cp_async16(dB + r * 80 + q * 16, Wp + (size_t)r * wstride + koff + q * 8);
    }
    cp_commit();
}

__global__ void __launch_bounds__(256)
bmma_gemm(const __nv_bfloat16* __restrict__ A0,
          const __nv_bfloat16* __restrict__ A1,
          const __nv_bfloat16* __restrict__ W, int wstride,
          const float* __restrict__ bias, const float* __restrict__ resid,
          float* __restrict__ out0, float* __restrict__ out1,
          int nrows, int mode)
{
    __shared__ __nv_bfloat16 sA[2][SBUF];
    __shared__ __nv_bfloat16 sB[2][SBUF];

    int t = threadIdx.x;
    int warp = t >> 5, lane = t & 31;
    int wm = warp & 3, wn = warp >> 2;       // 4 x 2 warp grid
    int g = lane >> 2, tg = lane & 3;
    int row0 = blockIdx.x * 128;
    const __nv_bfloat16* Wp = W + (size_t)(blockIdx.y * 128) * wstride;

    int nsteps = (A1 != nullptr) ? 24 : 12;

    float acc[2][8][4];
    #pragma unroll
    for (int i = 0; i < 2; i++)
        #pragma unroll
        for (int j = 0; j < 8; j++)
            #pragma unroll
            for (int k = 0; k < 4; k++) acc[i][j][k] = 0.f;

    uint32_t sAu = smem_u32(&sA[0][0]);
    uint32_t sBu = smem_u32(&sB[0][0]);

    stage_load(0, t, row0, nrows, A0, A1, Wp, wstride, sAu, sBu);

    for (int s = 0; s < nsteps; ++s) {
        if (s + 1 < nsteps) {
            stage_load(s + 1, t, row0, nrows, A0, A1, Wp, wstride, sAu, sBu);
            cp_wait<1>();
        } else {
            cp_wait<0>();
        }
        __syncthreads();

        const __nv_bfloat16* pA = sA[s & 1];
        const __nv_bfloat16* pB = sB[s & 1];
        #pragma unroll
        for (int ks = 0; ks < 32; ks += 16) {
            uint32_t aF[2][4];
            #pragma unroll
            for (int mi = 0; mi < 2; mi++) {
                int mb = (wm * 32 + mi * 16 + g) * SROW + ks + tg * 2;
                aF[mi][0] = *(const uint32_t*)(pA + mb);
                aF[mi][1] = *(const uint32_t*)(pA + mb + 8 * SROW);
                aF[mi][2] = *(const uint32_t*)(pA + mb + 8);
                aF[mi][3] = *(const uint32_t*)(pA + mb + 8 * SROW + 8);
            }
            #pragma unroll
            for (int ni = 0; ni < 8; ni++) {
                int nb = (wn * 64 + ni * 8 + g) * SROW + ks + tg * 2;
                uint32_t b0 = *(const uint32_t*)(pB + nb);
                uint32_t b1 = *(const uint32_t*)(pB + nb + 8);
                mma16816(acc[0][ni], aF[0], b0, b1);
                mma16816(acc[1][ni], aF[1], b0, b1);
            }
        }
        __syncthreads();
    }

    // ---- epilogue ----
    float* dst = out0;
    const float* bi = nullptr;
    const float* rs = nullptr;
    bool dorelu = false;
    if (mode == 1) {
        if (blockIdx.y == 1) { dst = out1; bi = bias; }
    } else if (mode == 2) {
        bi = bias; rs = resid; dorelu = true;
    }

    #pragma unroll
    for (int mi = 0; mi < 2; mi++) {
        #pragma unroll
        for (int ni = 0; ni < 8; ni++) {
            int colb = wn * 64 + ni * 8 + tg * 2;
            float bx = 0.f, by = 0.f;
            if (bi) { bx = __ldg(bi + colb); by = __ldg(bi + colb + 1); }
            int r1 = row0 + wm * 32 + mi * 16 + g;
            int r2 = r1 + 8;
            if (r1 < nrows) {
                float vx = acc[mi][ni][0] + bx;
                float vy = acc[mi][ni][1] + by;
                if (dorelu) { vx = fmaxf(vx, 0.f); vy = fmaxf(vy, 0.f); }
                if (rs) {
                    vx += rs[(size_t)r1 * HD + colb];
                    vy += rs[(size_t)r1 * HD + colb + 1];
                }
                float2 v = make_float2(vx, vy);
                *(float2*)(dst + (size_t)r1 * HD + colb) = v;
            }
            if (r2 < nrows) {
                float vx = acc[mi][ni][2] + bx;
                float vy = acc[mi][ni][3] + by;
                if (dorelu) { vx = fmaxf(vx, 0.f); vy = fmaxf(vy, 0.f); }
                if (rs) {
                    vx += rs[(size_t)r2 * HD + colb];
                    vy += rs[(size_t)r2 * HD + colb + 1];
                }
                float2 v = make_float2(vx, vy);
                *(float2*)(dst + (size_t)r2 * HD + colb) = v;
            }
        }
    }
}

// ---------------- weight prep: transpose + bf16 hi/lo, augmented layout -------
__global__ void prep_w(const float* __restrict__ wm1, const float* __restrict__ wm2,
                       const float* __restrict__ wr1, const float* __restrict__ wr2,
                       const float* __restrict__ wu1, const float* __restrict__ wu2)
{
    int slot = blockIdx.y;   // 0,1: AB per layer; 2,3: RES; 4,5: UPD
    int idx = blockIdx.x * 256 + threadIdx.x;
    if (slot < 2) {
        if (idx >= 256 * 128) return;
        int n = idx >> 7, k = idx & 127;
        const float* wm = slot ? wm2 : wm1;
        float v = (n < 128) ? wm[k * 128 + n] : wm[(128 + k) * 128 + (n - 128)];
        __nv_bfloat16 h = __float2bfloat16(v);
        __nv_bfloat16 l = __float2bfloat16(v - __bfloat162float(h));
        __nv_bfloat16* d = g_wab[slot];
        size_t base = (size_t)n * 384;
        d[base + k] = h; d[base + 128 + k] = h; d[base + 256 + k] = l;
    } else if (slot < 4) {
        if (idx >= 128 * 128) return;
        int n = idx >> 7, k = idx & 127;
        const float* wr = (slot == 3) ? wr2 : wr1;
        float v = wr[k * 128 + n];
        __nv_bfloat16 h = __float2bfloat16(v);
        __nv_bfloat16 l = __float2bfloat16(v - __bfloat162float(h));
        __nv_bfloat16* d = g_wres[slot - 2];
        size_t base = (size_t)n * 384;
        d[base + k] = h; d[base + 128 + k] = h; d[base + 256 + k] = l;
    } else {
        if (idx >= 128 * 256) return;
        int n = idx >> 8, k = idx & 255;
        const float* wu = (slot == 5) ? wu2 : wu1;
        float v = wu[k * 128 + n];
        __nv_bfloat16 h = __float2bfloat16(v);
        __nv_bfloat16 l = __float2bfloat16(v - __bfloat162float(h));
        __nv_bfloat16* d = g_wupd[slot - 4];
        int part = k >> 7, kk = k & 127;
        size_t base = (size_t)n * 768 + part * 384;
        d[base + kk] = h; d[base + 128 + kk] = h; d[base + 256 + kk] = l;
    }
}

// ---------------- fp32 -> augmented bf16 [hi|lo|hi] ---------------------------
__global__ void conv_split(const float* __restrict__ in,
                           __nv_bfloat16* __restrict__ aug, int ntasks)
{
    int i = blockIdx.x * blockDim.x + threadIdx.x;
    int stride = gridDim.x * blockDim.x;
    for (; i < ntasks; i += stride) {
        int r = i >> 5;
        int c = (i & 31) * 4;
        float4 v = *(const float4*)(in + (size_t)r * HD + c);
        __nv_bfloat16 h0 = __float2bfloat16(v.x), h1 = __float2bfloat16(v.y);
        __nv_bfloat16 h2 = __float2bfloat16(v.z), h3 = __float2bfloat16(v.w);
        __nv_bfloat16 l0 = __float2bfloat16(v.x - __bfloat162float(h0));
        __nv_bfloat16 l1 = __float2bfloat16(v.y - __bfloat162float(h1));
        __nv_bfloat16 l2 = __float2bfloat16(v.z - __bfloat162float(h2));
        __nv_bfloat16 l3 = __float2bfloat16(v.w - __bfloat162float(h3));
        __nv_bfloat162 hh0(h0, h1), hh1(h2, h3), ll0(l0, l1), ll1(l2, l3);
        uint2 hbits = make_uint2(*(uint32_t*)&hh0, *(uint32_t*)&hh1);
        uint2 lbits = make_uint2(*(uint32_t*)&ll0, *(uint32_t*)&ll1);
        __nv_bfloat16* base = aug + (size_t)r * 384;
        *(uint2*)(base + c)       = hbits;
        *(uint2*)(base + 128 + c) = lbits;
        *(uint2*)(base + 256 + c) = hbits;
    }
}

// ---------------- zero kernel -------------------------------------------------
__global__ void zero_kernel(float* __restrict__ p, int n4) {
    int i = blockIdx.x * blockDim.x + threadIdx.x;
    int stride = gridDim.x * blockDim.x;
    float4 z = make_float4(0.f, 0.f, 0.f, 0.f);
    for (; i < n4; i += stride) ((float4*)p)[i] = z;
}

// ---------------- per-edge message + scatter (proven, at L2 roofline) ---------
__global__ void __launch_bounds__(256)
edge_kernel(const float* __restrict__ A, const float* __restrict__ B,
            const float* __restrict__ dist,
            const int* __restrict__ row, const int* __restrict__ col,
            const float* __restrict__ wd,
            float* __restrict__ aggr, int nedges)
{
    __shared__ __align__(16) float swd[HD];
    int t = threadIdx.x;
    if (t < HD) swd[t] = wd[t];
    __syncthreads();

    int lane = t & 31;
    int f = lane * 4;
    float4 w = *(const float4*)(swd + f);

    int gw = blockIdx.x * 8 + (t >> 5);
    int e0 = gw * 2;
    if (e0 >= nedges) return;
    int e1 = e0 + 1;
    bool has1 = (e1 < nedges);

    int   r0 = __ldg(row + e0);
    int   c0 = __ldg(col + e0);
    float d0 = __ldg(dist + e0);
    int   r1 = has1 ? __ldg(row + e1) : r0;
    int   c1 = has1 ? __ldg(col + e1) : c0;
    float d1 = has1 ? __ldg(dist + e1) : 0.f;

    float4 a0 = *(const float4*)(A + (size_t)r0 * HD + f);
    float4 b0 = *(const float4*)(B + (size_t)c0 * HD + f);
    float4 a1 = *(const float4*)(A + (size_t)r1 * HD + f);
    float4 b1 = *(const float4*)(B + (size_t)c1 * HD + f);

    float4 m0, m1;
    m0.x = fmaxf(fmaf(d0, w.x, a0.x + b0.x), 0.f);
    m0.y = fmaxf(fmaf(d0, w.y, a0.y + b0.y), 0.f);
    m0.z = fmaxf(fmaf(d0, w.z, a0.z + b0.z), 0.f);
    m0.w = fmaxf(fmaf(d0, w.w, a0.w + b0.w), 0.f);
    m1.x = fmaxf(fmaf(d1, w.x, a1.x + b1.x), 0.f);
    m1.y = fmaxf(fmaf(d1, w.y, a1.y + b1.y), 0.f);
    m1.z = fmaxf(fmaf(d1, w.z, a1.z + b1.z), 0.f);
    m1.w = fmaxf(fmaf(d1, w.w, a1.w + b1.w), 0.f);

    red_add_v4(aggr + (size_t)c0 * HD + f, m0);
    if (has1) red_add_v4(aggr + (size_t)c1 * HD + f, m1);
}

// ---------------- per-graph pooling ------------------------------------------
__global__ void __launch_bounds__(256)
pool_kernel(const float* __restrict__ h, const int* __restrict__ batch,
            float* __restrict__ pool, int n)
{
    int warp = (blockIdx.x * blockDim.x + threadIdx.x) >> 5;
    int lane = threadIdx.x & 31;
    if (warp >= n) return;
    int g = __ldg(batch + warp);
    float4 v = *(const float4*)(h + (size_t)warp * HD + lane * 4);
    red_add_v4(pool + (size_t)g * HD + lane * 4, v);
}

// ---------------- prediction head --------------------------------------------
__global__ void __launch_bounds__(128)
head_kernel(const float* __restrict__ pool,
            const float* __restrict__ wp1, const float* __restrict__ bp1,
            const float* __restrict__ wp2, const float* __restrict__ bp2,
            float* __restrict__ out)
{
    int b = blockIdx.x;
    int t = threadIdx.x;
    __shared__ float sg[HD];
    __shared__ float red[HD];

    sg[t] = pool[(size_t)b * HD + t];
    __syncthreads();

    float acc = bp1[t];
    #pragma unroll 8
    for (int k = 0; k < HD; k++)
        acc = fmaf(sg[k], wp1[(size_t)k * HD + t], acc);
    acc = fmaxf(acc, 0.f) * wp2[t];

    red[t] = acc;
    __syncthreads();
    for (int s = 64; s > 0; s >>= 1) {
        if (t < s) red[t] += red[t + s];
        __syncthreads();
    }
    if (t == 0) out[b] = red[0] + bp2[0];
}

// ---------------- host side ---------------------------------------------------
extern "C" void kernel_launch(void* const* d_in, const int* in_sizes, int n_in,
                              void* d_out, int out_size)
{
    const float* x      = (const float*)d_in[0];
    const float* edist  = (const float*)d_in[1];
    const int*   eidx   = (const int*)  d_in[2];
    const int*   batch  = (const int*)  d_in[3];
    const float* wres1  = (const float*)d_in[4];
    const float* wmsg1  = (const float*)d_in[5];
    const float* bmsg1  = (const float*)d_in[6];
    const float* wupd1  = (const float*)d_in[7];
    const float* bupd1  = (const float*)d_in[8];
    const float* wres2  = (const float*)d_in[9];
    const float* wmsg2  = (const float*)d_in[10];
    const float* bmsg2  = (const float*)d_in[11];
    const float* wupd2  = (const float*)d_in[12];
    const float* bupd2  = (const float*)d_in[13];
    const float* wp1    = (const float*)d_in[14];
    const float* bp1    = (const float*)d_in[15];
    const float* wp2    = (const float*)d_in[16];
    const float* bp2    = (const float*)d_in[17];
    float* out = (float*)d_out;

    int N = in_sizes[0] / HD;
    int E = in_sizes[1];
    int G = out_size;   // T == 1
    const int* erow = eidx;
    const int* ecol = eidx + E;

    float *A, *B, *AG, *H1, *R, *H2, *P;
    __nv_bfloat16 *XAUG, *GAUG, *WAB, *WRES, *WUPD;
    cudaGetSymbolAddress((void**)&A,  g_A);
    cudaGetSymbolAddress((void**)&B,  g_Bv);
    cudaGetSymbolAddress((void**)&AG, g_aggr);
    cudaGetSymbolAddress((void**)&H1, g_h1);
    cudaGetSymbolAddress((void**)&R,  g_R);
    cudaGetSymbolAddress((void**)&H2, g_h2);
    cudaGetSymbolAddress((void**)&P,  g_pool);
    cudaGetSymbolAddress((void**)&XAUG, g_xaug);
    cudaGetSymbolAddress((void**)&GAUG, g_gaug);
    cudaGetSymbolAddress((void**)&WAB,  g_wab);
    cudaGetSymbolAddress((void**)&WRES, g_wres);
    cudaGetSymbolAddress((void**)&WUPD, g_wupd);
    __nv_bfloat16* WAB1  = WAB  + (size_t)256 * 384;
    __nv_bfloat16* WRES1 = WRES + (size_t)128 * 384;
    __nv_bfloat16* WUPD1 = WUPD + (size_t)128 * 768;

    int nblk = (N + 127) / 128;
    int edge_blocks = (E + 15) / 16;
    int nh4 = (N * HD) / 4;

    // weight prep (transpose + split + augment)
    {
        dim3 gp(128, 6);
        prep_w<<<gp, 256>>>(wmsg1, wmsg2, wres1, wres2, wupd1, wupd2);
    }

    dim3 gab(nblk, 2), g1(nblk, 1);

    // ---------- layer 1 ----------
    conv_split<<<1024, 256>>>(x, XAUG, N * 32);
    zero_kernel<<<1024, 256>>>(AG, nh4);
    bmma_gemm<<<gab, 256>>>(XAUG, nullptr, WAB,  384, bmsg1, nullptr, A, B, N, 1);
    edge_kernel<<<edge_blocks, 256>>>(A, B, edist, erow, ecol, wmsg1 + 256 * HD, AG, E);
    bmma_gemm<<<g1, 256>>>(XAUG, nullptr, WRES, 384, nullptr, nullptr, R, nullptr, N, 0);
    conv_split<<<1024, 256>>>(AG, GAUG, N * 32);
    bmma_gemm<<<g1, 256>>>(XAUG, GAUG, WUPD, 768, bupd1, R, H1, nullptr, N, 2);

    // ---------- layer 2 ----------
    conv_split<<<1024, 256>>>(H1, XAUG, N * 32);
    zero_kernel<<<1024, 256>>>(AG, nh4);
    bmma_gemm<<<gab, 256>>>(XAUG, nullptr, WAB1, 384, bmsg2, nullptr, A, B, N, 1);
    edge_kernel<<<edge_blocks, 256>>>(A, B, edist, erow, ecol, wmsg2 + 256 * HD, AG, E);
    bmma_gemm<<<g1, 256>>>(XAUG, nullptr, WRES1, 384, nullptr, nullptr, R, nullptr, N, 0);
    conv_split<<<1024, 256>>>(AG, GAUG, N * 32);
    bmma_gemm<<<g1, 256>>>(XAUG, GAUG, WUPD1, 768, bupd2, R, H2, nullptr, N, 2);

    // ---------- pooling + head ----------
    zero_kernel<<<4, 256>>>(P, (G * HD) / 4);
    int pool_blocks = (N * 32 + 255) / 256;
    pool_kernel<<<pool_blocks, 256>>>(H2, batch, P, N);
    head_kernel<<<G, 128>>>(P, wp1, bp1, wp2, bp2, out);
}

// round 7
// speedup vs baseline: 1.6227x; 1.0279x over previous
#include <cuda_runtime.h>
#include <cuda_bf16.h>
#include <cstdint>

#define HD 128
#define MAXN 50000
#define MAXG 64

// ---------------- scratch (static __device__ arrays; no allocation) ----------
__device__ __align__(16) float g_A   [(size_t)MAXN * HD];
__device__ __align__(16) float g_Bv  [(size_t)MAXN * HD];
__device__ __align__(16) float g_aggr[(size_t)MAXN * HD];
__device__ __align__(16) float g_h1  [(size_t)MAXN * HD];
__device__ __align__(16) float g_R   [(size_t)MAXN * HD];
__device__ __align__(16) float g_h2  [(size_t)MAXN * HD];
__device__ __align__(16) float g_pool[(size_t)MAXG * HD];
// augmented bf16 activations: [n, 384] = [hi(128) | lo(128) | hi(128)]
__device__ __align__(16) __nv_bfloat16 g_xaug[(size_t)MAXN * 384];
__device__ __align__(16) __nv_bfloat16 g_gaug[(size_t)MAXN * 384];
// augmented weights, [n, k'] row-major
__device__ __align__(16) __nv_bfloat16 g_wabr[2][384 * 384];
__device__ __align__(16) __nv_bfloat16 g_wupd[2][128 * 768];

// ---------------- helpers ----------------------------------------------------
__device__ __forceinline__ void red_add_v4(float* dst, float4 v) {
    asm volatile("red.global.add.v4.f32 [%0], {%1,%2,%3,%4};"
                 :: "l"(dst), "f"(v.x), "f"(v.y), "f"(v.z), "f"(v.w) : "memory");
}
__device__ __forceinline__ uint32_t smem_u32(const void* p) {
    uint32_t a;
    asm("{ .reg .u64 t; cvta.to.shared.u64 t, %1; cvt.u32.u64 %0, t; }"
        : "=r"(a) : "l"(p));
    return a;
}
__device__ __forceinline__ void cp_async16(uint32_t dst, const void* src) {
    asm volatile("cp.async.ca.shared.global [%0], [%1], 16;"
                 :: "r"(dst), "l"(src) : "memory");
}
__device__ __forceinline__ void cp_commit() {
    asm volatile("cp.async.commit_group;" ::: "memory");
}
template <int N>
__device__ __forceinline__ void cp_wait() {
    asm volatile("cp.async.wait_group %0;" :: "n"(N) : "memory");
}
__device__ __forceinline__ void ldmatrix_x4(uint32_t* r, uint32_t addr) {
    asm volatile("ldmatrix.sync.aligned.m8n8.x4.shared.b16 {%0,%1,%2,%3}, [%4];"
                 : "=r"(r[0]), "=r"(r[1]), "=r"(r[2]), "=r"(r[3]) : "r"(addr));
}
__device__ __forceinline__ void mma16816(float* d, const uint32_t* a,
                                         uint32_t b0, uint32_t b1) {
    asm volatile("mma.sync.aligned.m16n8k16.row.col.f32.bf16.bf16.f32 "
                 "{%0,%1,%2,%3}, {%4,%5,%6,%7}, {%8,%9}, {%0,%1,%2,%3};"
                 : "+f"(d[0]), "+f"(d[1]), "+f"(d[2]), "+f"(d[3])
                 : "r"(a[0]), "r"(a[1]), "r"(a[2]), "r"(a[3]),
                   "r"(b0), "r"(b1));
}

// ---------------- bf16 tensor-core GEMM ---------------------------------------
// 128x128 tile, 8 warps (4m x 2n), warp tile 32x64, BK=32, 3-stage cp.async,
// ldmatrix frag loads. smem rows padded to 40 bf16 (80 B) -> conflict-free.
// mode 1 (ABR): K'=384, grid.y: 0->outA, 1->outB(+bias), 2->outR
// mode 2 (UPD): K'=768 (A0 then A1), out = resid + relu(acc + bias)
#define SROW 40
#define SBUFB (128 * SROW * 2)          // 10240 bytes per stage per operand
#define STAGES 3
#define GEMM_SMEM (STAGES * SBUFB * 2)  // 61440 bytes

__device__ __forceinline__ void stage_load(
    int s, int t, int row0, int nrows,
    const __nv_bfloat16* __restrict__ A0, const __nv_bfloat16* __restrict__ A1,
    const __nv_bfloat16* __restrict__ Wp, int wstride,
    uint32_t smbase)
{
    int buf = s % STAGES;
    int kk = (s % 12) * 32;
    int koff = (s / 12) * 384 + kk;
    const __nv_bfloat16* Asrc = (s < 12) ? A0 : A1;
    uint32_t dA = smbase + (uint32_t)buf * SBUFB;
    uint32_t dB = smbase + (uint32_t)(STAGES * SBUFB) + (uint32_t)buf * SBUFB;
    #pragma unroll
    for (int i = t * 2; i < t * 2 + 2; i++) {
        int r = i >> 2, q = i & 3;              // 128 rows x 4 quads
        int gr = row0 + r; if (gr >= nrows) gr = nrows - 1;
        cp_async16(dA + r * 80 + q * 16, Asrc + (size_t)gr * 384 + kk + q * 8);
        cp_async16(dB + r * 80 + q * 16, Wp + (size_t)r * wstride + koff + q * 8);
    }
    cp_commit();
}

__global__ void __launch_bounds__(256)
bmma_gemm(const __nv_bfloat16* __restrict__ A0,
          const __nv_bfloat16* __restrict__ A1,
          const __nv_bfloat16* __restrict__ W, int wstride,
          const float* __restrict__ bias, const float* __restrict__ resid,
          float* __restrict__ outA, float* __restrict__ outB,
          float* __restrict__ outR, int nrows, int mode)
{
    extern __shared__ char smraw[];
    uint32_t smbase = smem_u32(smraw);

    int t = threadIdx.x;
    int warp = t >> 5, lane = t & 31;
    int wm = warp & 3, wn = warp >> 2;       // 4 x 2 warp grid
    int g = lane >> 2, tg = lane & 3;
    int row0 = blockIdx.x * 128;
    const __nv_bfloat16* Wp = W + (size_t)(blockIdx.y * 128) * wstride;

    int nsteps = (mode == 2) ? 24 : 12;

    float acc[2][8][4];
    #pragma unroll
    for (int i = 0; i < 2; i++)
        #pragma unroll
        for (int j = 0; j < 8; j++)
            #pragma unroll
            for (int k = 0; k < 4; k++) acc[i][j][k] = 0.f;

    // per-lane invariant ldmatrix offsets (bytes)
    uint32_t aLane = (uint32_t)(((lane & 15) * SROW + (lane >> 4) * 8) * 2);
    uint32_t bLane = (uint32_t)((((lane >> 4) * 8 + (lane & 7)) * SROW
                               + ((lane >> 3) & 1) * 8) * 2);

    // prologue: stages 0,1
    stage_load(0, t, row0, nrows, A0, A1, Wp, wstride, smbase);
    stage_load(1, t, row0, nrows, A0, A1, Wp, wstride, smbase);

    for (int s = 0; s < nsteps; ++s) {
        cp_wait<1>();
        __syncthreads();
        if (s + 2 < nsteps)
            stage_load(s + 2, t, row0, nrows, A0, A1, Wp, wstride, smbase);
        else
            cp_commit();   // empty group keeps wait<1> semantics uniform

        int buf = s % STAGES;
        uint32_t bufA = smbase + (uint32_t)buf * SBUFB;
        uint32_t bufB = smbase + (uint32_t)(STAGES * SBUFB) + (uint32_t)buf * SBUFB;

        #pragma unroll
        for (int ks = 0; ks < 32; ks += 16) {
            uint32_t aF[2][4];
            #pragma unroll
            for (int mi = 0; mi < 2; mi++)
                ldmatrix_x4(aF[mi],
                    bufA + (uint32_t)(((wm * 32 + mi * 16) * SROW + ks) * 2) + aLane);
            uint32_t bF[8][2];
            #pragma unroll
            for (int p = 0; p < 4; p++) {
                uint32_t r[4];
                ldmatrix_x4(r,
                    bufB + (uint32_t)(((wn * 64 + p * 16) * SROW + ks) * 2) + bLane);
                bF[2 * p][0] = r[0]; bF[2 * p][1] = r[1];
                bF[2 * p + 1][0] = r[2]; bF[2 * p + 1][1] = r[3];
            }
            #pragma unroll
            for (int ni = 0; ni < 8; ni++) {
                mma16816(acc[0][ni], aF[0], bF[ni][0], bF[ni][1]);
                mma16816(acc[1][ni], aF[1], bF[ni][0], bF[ni][1]);
            }
        }
    }

    // ---- epilogue ----
    float* dst;
    const float* bi = nullptr;
    const float* rs = nullptr;
    bool dorelu = false;
    if (mode == 1) {
        if (blockIdx.y == 0)      dst = outA;
        else if (blockIdx.y == 1) { dst = outB; bi = bias; }
        else                      dst = outR;
    } else {
        dst = outA; bi = bias; rs = resid; dorelu = true;
    }

    #pragma unroll
    for (int mi = 0; mi < 2; mi++) {
        #pragma unroll
        for (int ni = 0; ni < 8; ni++) {
            int colb = wn * 64 + ni * 8 + tg * 2;
            float bx = 0.f, by = 0.f;
            if (bi) { bx = __ldg(bi + colb); by = __ldg(bi + colb + 1); }
            int r1 = row0 + wm * 32 + mi * 16 + g;
            int r2 = r1 + 8;
            if (r1 < nrows) {
                float vx = acc[mi][ni][0] + bx;
                float vy = acc[mi][ni][1] + by;
                if (dorelu) { vx = fmaxf(vx, 0.f); vy = fmaxf(vy, 0.f); }
                if (rs) {
                    vx += rs[(size_t)r1 * HD + colb];
                    vy += rs[(size_t)r1 * HD + colb + 1];
                }
                *(float2*)(dst + (size_t)r1 * HD + colb) = make_float2(vx, vy);
            }
            if (r2 < nrows) {
                float vx = acc[mi][ni][2] + bx;
                float vy = acc[mi][ni][3] + by;
                if (dorelu) { vx = fmaxf(vx, 0.f); vy = fmaxf(vy, 0.f); }
                if (rs) {
                    vx += rs[(size_t)r2 * HD + colb];
                    vy += rs[(size_t)r2 * HD + colb + 1];
                }
                *(float2*)(dst + (size_t)r2 * HD + colb) = make_float2(vx, vy);
            }
        }
    }
}

// ---------------- weight prep: transpose + bf16 hi/lo, augmented layout -------
// slots 0,1: ABR weights [384 n][384 k']; slots 2,3: UPD [128 n][768 k']
__global__ void prep_w(const float* __restrict__ wm1, const float* __restrict__ wm2,
                       const float* __restrict__ wr1, const float* __restrict__ wr2,
                       const float* __restrict__ wu1, const float* __restrict__ wu2)
{
    int slot = blockIdx.y;
    int idx = blockIdx.x * 256 + threadIdx.x;
    if (slot < 2) {
        if (idx >= 384 * 384) return;
        int n = idx / 384, k = idx % 384;
        int kb = k & 127, seg = k >> 7;
        const float* wm = slot ? wm2 : wm1;
        const float* wr = slot ? wr2 : wr1;
        float v;
        if (n < 128)       v = wm[kb * 128 + n];
        else if (n < 256)  v = wm[(128 + kb) * 128 + (n - 128)];
        else               v = wr[kb * 128 + (n - 256)];
        __nv_bfloat16 h = __float2bfloat16(v);
        g_wabr[slot][idx] = (seg == 2)
            ? __float2bfloat16(v - __bfloat162float(h)) : h;
    } else {
        if (idx >= 128 * 768) return;
        int n = idx / 768, k = idx % 768;
        int part = k / 384;                 // 0: X terms, 1: AG terms
        int kb = k & 127, seg = (k % 384) >> 7;
        const float* wu = (slot == 3) ? wu2 : wu1;
        float v = wu[(part * 128 + kb) * 128 + n];
        __nv_bfloat16 h = __float2bfloat16(v);
        g_wupd[slot - 2][idx] = (seg == 2)
            ? __float2bfloat16(v - __bfloat162float(h)) : h;
    }
}

// ---------------- fp32 -> augmented bf16 [hi|lo|hi] ---------------------------
__global__ void conv_split(const float* __restrict__ in,
                           __nv_bfloat16* __restrict__ aug, int ntasks)
{
    int i = blockIdx.x * blockDim.x + threadIdx.x;
    int stride = gridDim.x * blockDim.x;
    for (; i < ntasks; i += stride) {
        int r = i >> 5;
        int c = (i & 31) * 4;
        float4 v = *(const float4*)(in + (size_t)r * HD + c);
        __nv_bfloat16 h0 = __float2bfloat16(v.x), h1 = __float2bfloat16(v.y);
        __nv_bfloat16 h2 = __float2bfloat16(v.z), h3 = __float2bfloat16(v.w);
        __nv_bfloat16 l0 = __float2bfloat16(v.x - __bfloat162float(h0));
        __nv_bfloat16 l1 = __float2bfloat16(v.y - __bfloat162float(h1));
        __nv_bfloat16 l2 = __float2bfloat16(v.z - __bfloat162float(h2));
        __nv_bfloat16 l3 = __float2bfloat16(v.w - __bfloat162float(h3));
        __nv_bfloat162 hh0(h0, h1), hh1(h2, h3), ll0(l0, l1), ll1(l2, l3);
        uint2 hbits = make_uint2(*(uint32_t*)&hh0, *(uint32_t*)&hh1);
        uint2 lbits = make_uint2(*(uint32_t*)&ll0, *(uint32_t*)&ll1);
        __nv_bfloat16* base = aug + (size_t)r * 384;
        *(uint2*)(base + c)       = hbits;
        *(uint2*)(base + 128 + c) = lbits;
        *(uint2*)(base + 256 + c) = hbits;
    }
}

// ---------------- zero kernel -------------------------------------------------
__global__ void zero_kernel(float* __restrict__ p, int n4) {
    int i = blockIdx.x * blockDim.x + threadIdx.x;
    int stride = gridDim.x * blockDim.x;
    float4 z = make_float4(0.f, 0.f, 0.f, 0.f);
    for (; i < n4; i += stride) ((float4*)p)[i] = z;
}

// ---------------- per-edge message + scatter (proven, at L2 roofline) ---------
__global__ void __launch_bounds__(256)
edge_kernel(const float* __restrict__ A, const float* __restrict__ B,
            const float* __restrict__ dist,
            const int* __restrict__ row, const int* __restrict__ col,
            const float* __restrict__ wd,
            float* __restrict__ aggr, int nedges)
{
    __shared__ __align__(16) float swd[HD];
    int t = threadIdx.x;
    if (t < HD) swd[t] = wd[t];
    __syncthreads();

    int lane = t & 31;
    int f = lane * 4;
    float4 w = *(const float4*)(swd + f);

    int gw = blockIdx.x * 8 + (t >> 5);
    int e0 = gw * 2;
    if (e0 >= nedges) return;
    int e1 = e0 + 1;
    bool has1 = (e1 < nedges);

    int   r0 = __ldg(row + e0);
    int   c0 = __ldg(col + e0);
    float d0 = __ldg(dist + e0);
    int   r1 = has1 ? __ldg(row + e1) : r0;
    int   c1 = has1 ? __ldg(col + e1) : c0;
    float d1 = has1 ? __ldg(dist + e1) : 0.f;

    float4 a0 = *(const float4*)(A + (size_t)r0 * HD + f);
    float4 b0 = *(const float4*)(B + (size_t)c0 * HD + f);
    float4 a1 = *(const float4*)(A + (size_t)r1 * HD + f);
    float4 b1 = *(const float4*)(B + (size_t)c1 * HD + f);

    float4 m0, m1;
    m0.x = fmaxf(fmaf(d0, w.x, a0.x + b0.x), 0.f);
    m0.y = fmaxf(fmaf(d0, w.y, a0.y + b0.y), 0.f);
    m0.z = fmaxf(fmaf(d0, w.z, a0.z + b0.z), 0.f);
    m0.w = fmaxf(fmaf(d0, w.w, a0.w + b0.w), 0.f);
    m1.x = fmaxf(fmaf(d1, w.x, a1.x + b1.x), 0.f);
    m1.y = fmaxf(fmaf(d1, w.y, a1.y + b1.y), 0.f);
    m1.z = fmaxf(fmaf(d1, w.z, a1.z + b1.z), 0.f);
    m1.w = fmaxf(fmaf(d1, w.w, a1.w + b1.w), 0.f);

    red_add_v4(aggr + (size_t)c0 * HD + f, m0);
    if (has1) red_add_v4(aggr + (size_t)c1 * HD + f, m1);
}

// ---------------- per-graph pooling ------------------------------------------
__global__ void __launch_bounds__(256)
pool_kernel(const float* __restrict__ h, const int* __restrict__ batch,
            float* __restrict__ pool, int n)
{
    int warp = (blockIdx.x * blockDim.x + threadIdx.x) >> 5;
    int lane = threadIdx.x & 31;
    if (warp >= n) return;
    int g = __ldg(batch + warp);
    float4 v = *(const float4*)(h + (size_t)warp * HD + lane * 4);
    red_add_v4(pool + (size_t)g * HD + lane * 4, v);
}

// ---------------- prediction head --------------------------------------------
__global__ void __launch_bounds__(128)
head_kernel(const float* __restrict__ pool,
            const float* __restrict__ wp1, const float* __restrict__ bp1,
            const float* __restrict__ wp2, const float* __restrict__ bp2,
            float* __restrict__ out)
{
    int b = blockIdx.x;
    int t = threadIdx.x;
    __shared__ float sg[HD];
    __shared__ float red[HD];

    sg[t] = pool[(size_t)b * HD + t];
    __syncthreads();

    float acc = bp1[t];
    #pragma unroll 8
    for (int k = 0; k < HD; k++)
        acc = fmaf(sg[k], wp1[(size_t)k * HD + t], acc);
    acc = fmaxf(acc, 0.f) * wp2[t];

    red[t] = acc;
    __syncthreads();
    for (int s = 64; s > 0; s >>= 1) {
        if (t < s) red[t] += red[t + s];
        __syncthreads();
    }
    if (t == 0) out[b] = red[0] + bp2[0];
}

// ---------------- host side ---------------------------------------------------
extern "C" void kernel_launch(void* const* d_in, const int* in_sizes, int n_in,
                              void* d_out, int out_size)
{
    const float* x      = (const float*)d_in[0];
    const float* edist  = (const float*)d_in[1];
    const int*   eidx   = (const int*)  d_in[2];
    const int*   batch  = (const int*)  d_in[3];
    const float* wres1  = (const float*)d_in[4];
    const float* wmsg1  = (const float*)d_in[5];
    const float* bmsg1  = (const float*)d_in[6];
    const float* wupd1  = (const float*)d_in[7];
    const float* bupd1  = (const float*)d_in[8];
    const float* wres2  = (const float*)d_in[9];
    const float* wmsg2  = (const float*)d_in[10];
    const float* bmsg2  = (const float*)d_in[11];
    const float* wupd2  = (const float*)d_in[12];
    const float* bupd2  = (const float*)d_in[13];
    const float* wp1    = (const float*)d_in[14];
    const float* bp1    = (const float*)d_in[15];
    const float* wp2    = (const float*)d_in[16];
    const float* bp2    = (const float*)d_in[17];
    float* out = (float*)d_out;

    int N = in_sizes[0] / HD;
    int E = in_sizes[1];
    int G = out_size;   // T == 1
    const int* erow = eidx;
    const int* ecol = eidx + E;

    float *A, *B, *AG, *H1, *R, *H2, *P;
    __nv_bfloat16 *XAUG, *GAUG, *WABR, *WUPD;
    cudaGetSymbolAddress((void**)&A,  g_A);
    cudaGetSymbolAddress((void**)&B,  g_Bv);
    cudaGetSymbolAddress((void**)&AG, g_aggr);
    cudaGetSymbolAddress((void**)&H1, g_h1);
    cudaGetSymbolAddress((void**)&R,  g_R);
    cudaGetSymbolAddress((void**)&H2, g_h2);
    cudaGetSymbolAddress((void**)&P,  g_pool);
    cudaGetSymbolAddress((void**)&XAUG, g_xaug);
    cudaGetSymbolAddress((void**)&GAUG, g_gaug);
    cudaGetSymbolAddress((void**)&WABR, g_wabr);
    cudaGetSymbolAddress((void**)&WUPD, g_wupd);
    __nv_bfloat16* WABR1 = WABR + (size_t)384 * 384;
    __nv_bfloat16* WUPD1 = WUPD + (size_t)128 * 768;

    cudaFuncSetAttribute((const void*)bmma_gemm,
                         cudaFuncAttributeMaxDynamicSharedMemorySize, GEMM_SMEM);

    int nblk = (N + 127) / 128;
    int edge_blocks = (E + 15) / 16;
    int nh4 = (N * HD) / 4;

    // weight prep (transpose + split + augment)
    {
        dim3 gp(576, 4);
        prep_w<<<gp, 256>>>(wmsg1, wmsg2, wres1, wres2, wupd1, wupd2);
    }

    dim3 gabr(nblk, 3), g1(nblk, 1);

    // ---------- layer 1 ----------
    conv_split<<<1024, 256>>>(x, XAUG, N * 32);
    zero_kernel<<<1024, 256>>>(AG, nh4);
    bmma_gemm<<<gabr, 256, GEMM_SMEM>>>(XAUG, nullptr, WABR, 384, bmsg1, nullptr,
                                        A, B, R, N, 1);
    edge_kernel<<<edge_blocks, 256>>>(A, B, edist, erow, ecol, wmsg1 + 256 * HD, AG, E);
    conv_split<<<1024, 256>>>(AG, GAUG, N * 32);
    bmma_gemm<<<g1, 256, GEMM_SMEM>>>(XAUG, GAUG, WUPD, 768, bupd1, R,
                                      H1, nullptr, nullptr, N, 2);

    // ---------- layer 2 ----------
    conv_split<<<1024, 256>>>(H1, XAUG, N * 32);
    zero_kernel<<<1024, 256>>>(AG, nh4);
    bmma_gemm<<<gabr, 256, GEMM_SMEM>>>(XAUG, nullptr, WABR1, 384, bmsg2, nullptr,
                                        A, B, R, N, 1);
    edge_kernel<<<edge_blocks, 256>>>(A, B, edist, erow, ecol, wmsg2 + 256 * HD, AG, E);
    conv_split<<<1024, 256>>>(AG, GAUG, N * 32);
    bmma_gemm<<<g1, 256, GEMM_SMEM>>>(XAUG, GAUG, WUPD1, 768, bupd2, R,
                                      H2, nullptr, nullptr, N, 2);

    // ---------- pooling + head ----------
    zero_kernel<<<4, 256>>>(P, (G * HD) / 4);
    int pool_blocks = (N * 32 + 255) / 256;
    pool_kernel<<<pool_blocks, 256>>>(H2, batch, P, N);
    head_kernel<<<G, 128>>>(P, wp1, bp1, wp2, bp2, out);
}